// round 13
// baseline (speedup 1.0000x reference)
#include <cuda_runtime.h>
#include <cuda_fp16.h>

// ---------------------------------------------------------------------------
// out[4096,4096] = x @ sign(W) + b
// A = fp16(x), B = sign(W)^T fp16 (+-1 exact), fp32 acc, mma.sync m16n8k16.
// Persistent kernel (296 CTAs, 2/SM), dynamic tile stealing via device
// counter, cp.async pipeline carried ACROSS tile boundaries (no fill/drain
// per tile; epilogue overlaps next tile's loads).
// ---------------------------------------------------------------------------

#define DIMM 4096

constexpr int BM = 128;
constexpr int BN = 128;
constexpr int BK = 64;
constexpr int STAGES = 3;
constexpr int KITERS = DIMM / BK;                 // 64
constexpr int TILE_BYTES = 128 * 64 * 2;          // 16384
constexpr int STAGE_BYTES = 2 * TILE_BYTES;       // 32768 (A + B)
constexpr int SMEM_TOTAL = STAGES * STAGE_BYTES;  // 98304
constexpr int NTILES = 1024;
constexpr int GRID = 296;                         // 2 CTAs/SM * 148 SMs

// Scratch (__device__ globals: allocation-free)
__device__ __align__(1024) __half g_ST[(size_t)DIMM * DIMM];  // [N][K] sign(W)^T fp16
__device__ __align__(1024) __half g_xh[(size_t)DIMM * DIMM];  // [M][K] fp16(x)
__device__ int g_ctr;                                         // tile counter

// ------------------------- helpers -----------------------------------------

__device__ __forceinline__ unsigned smem_u32(const void* p) {
    unsigned a;
    asm("{ .reg .u64 t; cvta.to.shared.u64 t, %1; cvt.u32.u64 %0, t; }" : "=r"(a) : "l"(p));
    return a;
}
__device__ __forceinline__ unsigned sw128(unsigned off) { return off ^ ((off >> 3) & 0x70); }

__device__ __forceinline__ void cp16(unsigned dst, const void* src) {
    asm volatile("cp.async.cg.shared.global [%0], [%1], 16;" ::"r"(dst), "l"(src));
}
__device__ __forceinline__ void ldsm_x4(unsigned& r0, unsigned& r1, unsigned& r2, unsigned& r3,
                                        unsigned addr) {
    asm volatile("ldmatrix.sync.aligned.m8n8.x4.shared.b16 {%0,%1,%2,%3}, [%4];"
                 : "=r"(r0), "=r"(r1), "=r"(r2), "=r"(r3)
                 : "r"(addr));
}
__device__ __forceinline__ void mma_f16(float* d, const unsigned* a, const unsigned* b) {
    asm volatile(
        "mma.sync.aligned.m16n8k16.row.col.f32.f16.f16.f32 "
        "{%0,%1,%2,%3}, {%4,%5,%6,%7}, {%8,%9}, {%0,%1,%2,%3};"
        : "+f"(d[0]), "+f"(d[1]), "+f"(d[2]), "+f"(d[3])
        : "r"(a[0]), "r"(a[1]), "r"(a[2]), "r"(a[3]), "r"(b[0]), "r"(b[1]));
}

// Issue one stage's cp.asyncs (predicated) + ALWAYS commit a group so the
// wait_group accounting stays uniform (empty groups complete instantly).
__device__ __forceinline__ void load_stage(unsigned base, const char* gA, const char* gB,
                                           int kit, const unsigned* s_off,
                                           const unsigned* g_off, bool valid) {
    if (valid) {
        unsigned kb = (unsigned)kit * (BK * 2);
#pragma unroll
        for (int p = 0; p < 4; p++) {
            cp16(base + s_off[p], gA + kb + g_off[p]);
            cp16(base + TILE_BYTES + s_off[p], gB + kb + g_off[p]);
        }
    }
    asm volatile("cp.async.commit_group;");
}

// ------------------------- prep (one kernel) --------------------------------
// blocks [0,8192): x -> fp16, 8 elems/thread
// blocks [8192,12288): W -> transposed sign fp16 (64x64 tile, 128B stores)
__global__ void prep_kernel(const float* __restrict__ x, const float* __restrict__ W) {
    __shared__ float t[64][65];
    int bid = blockIdx.x;
    int tid = threadIdx.x;
    if (bid == 0 && tid == 0) g_ctr = 0;  // reset tile counter for bgemm
    if (bid < 8192) {
        size_t i = (size_t)bid * 2048 + tid * 8;
        const float4* xv = reinterpret_cast<const float4*>(x + i);
        float4 v0 = xv[0];
        float4 v1 = xv[1];
        union { unsigned u[4]; uint4 q; } o;
        __half2 h;
        h = __floats2half2_rn(v0.x, v0.y); o.u[0] = *reinterpret_cast<unsigned*>(&h);
        h = __floats2half2_rn(v0.z, v0.w); o.u[1] = *reinterpret_cast<unsigned*>(&h);
        h = __floats2half2_rn(v1.x, v1.y); o.u[2] = *reinterpret_cast<unsigned*>(&h);
        h = __floats2half2_rn(v1.z, v1.w); o.u[3] = *reinterpret_cast<unsigned*>(&h);
        *reinterpret_cast<uint4*>(g_xh + i) = o.q;
    } else {
        int b = bid - 8192;
        int nb = (b & 63) * 64, kb = (b >> 6) * 64;
        int tx = tid & 63, ty = tid >> 6;
#pragma unroll
        for (int i = 0; i < 16; i++) {
            int k = i * 4 + ty;
            float w = W[(size_t)(kb + k) * DIMM + nb + tx];
            t[k][tx] = (w > 0.f) ? 1.f : ((w < 0.f) ? -1.f : 0.f);
        }
        __syncthreads();
        int n = tid >> 2, q = tid & 3;
        union { __half h[16]; uint4 u[2]; } o;
#pragma unroll
        for (int j = 0; j < 16; j++) o.h[j] = __float2half(t[q * 16 + j][n]);
        uint4* dst = reinterpret_cast<uint4*>(g_ST + (size_t)(nb + n) * DIMM + kb + q * 16);
        dst[0] = o.u[0];
        dst[1] = o.u[1];
    }
}

// ------------------------- GEMM kernel (persistent) -------------------------
// grid = 296 CTAs; 256 threads (8 warps, 4m x 2n), warp tile 32x64, 2 CTAs/SM.
__global__ void __launch_bounds__(256, 2)
bgemm_kernel(const float* __restrict__ bias, float* __restrict__ out) {
    extern __shared__ char smem[];
    unsigned sb = smem_u32(smem);
    __shared__ int s_cur, s_next;
    int tid = threadIdx.x;
    int wid = tid >> 5, lane = tid & 31;
    int wm = wid & 3;   // 0..3
    int wn = wid >> 2;  // 0..1

    const char* baseA = reinterpret_cast<const char*>(g_xh);
    const char* baseB = reinterpret_cast<const char*>(g_ST);

    unsigned s_off[4];
    unsigned g_off[4];
#pragma unroll
    for (int p = 0; p < 4; p++) {
        int idx = p * 256 + tid;
        int row = idx >> 3, colb = (idx & 7) * 16;
        s_off[p] = sw128((unsigned)(row * 128 + colb));
        g_off[p] = (unsigned)(row * (DIMM * 2) + colb);
    }

    // first tile
    if (tid == 0) s_cur = atomicAdd(&g_ctr, 1);
    __syncthreads();
    int cur = s_cur;                      // grid(296) < NTILES so always valid
    if (tid == 0) s_next = atomicAdd(&g_ctr, 1);  // read only after kit-0 barrier

    const char* gA = baseA + (size_t)(cur & 31) * (BM * DIMM * 2);
    const char* gB = baseB + (size_t)(cur >> 5) * (BN * DIMM * 2);

    load_stage(sb + 0 * STAGE_BYTES, gA, gB, 0, s_off, g_off, true);
    load_stage(sb + 1 * STAGE_BYTES, gA, gB, 1, s_off, g_off, true);

    float acc[2][8][4];
#pragma unroll
    for (int mi = 0; mi < 2; mi++)
#pragma unroll
        for (int ni = 0; ni < 8; ni++)
#pragma unroll
            for (int c = 0; c < 4; c++) acc[mi][ni][c] = 0.f;

    int a_row = lane & 15;
    int a_colb = (lane >> 4) * 16;
    int b_row = ((lane >> 4) << 3) + (lane & 7);
    int b_colb = ((lane >> 3) & 1) * 16;

    int s = 0;
    while (true) {
#pragma unroll 1
        for (int kit = 0; kit < KITERS; kit++) {
            asm volatile("cp.async.wait_group 1;" ::: "memory");
            __syncthreads();

            unsigned sA = sb + s * STAGE_BYTES;
            unsigned sB = sA + TILE_BYTES;

#pragma unroll
            for (int kt = 0; kt < 4; kt++) {
                if (kt == 1) {
                    // prefetch kit+2; may belong to the NEXT tile
                    int lk = kit + 2;
                    unsigned dstage = sb + ((s + 2) % STAGES) * STAGE_BYTES;
                    if (lk < KITERS) {
                        load_stage(dstage, gA, gB, lk, s_off, g_off, true);
                    } else {
                        int nt = s_next;  // stable: written before this tile's kit0 barrier
                        bool v = nt < NTILES;
                        const char* nA = baseA + (size_t)(nt & 31) * (BM * DIMM * 2);
                        const char* nB = baseB + (size_t)((nt >> 5) & 31) * (BN * DIMM * 2);
                        load_stage(dstage, nA, nB, lk - KITERS, s_off, g_off, v);
                    }
                }
                unsigned a[2][4];
#pragma unroll
                for (int mi = 0; mi < 2; mi++) {
                    int mrow = wm * 32 + mi * 16 + a_row;
                    ldsm_x4(a[mi][0], a[mi][1], a[mi][2], a[mi][3],
                            sA + sw128((unsigned)(mrow * 128 + kt * 32 + a_colb)));
                }
                unsigned bfr[8][2];
#pragma unroll
                for (int nb = 0; nb < 4; nb++) {
                    int nrow = wn * 64 + nb * 16 + b_row;
                    ldsm_x4(bfr[2 * nb][0], bfr[2 * nb][1], bfr[2 * nb + 1][0],
                            bfr[2 * nb + 1][1],
                            sB + sw128((unsigned)(nrow * 128 + kt * 32 + b_colb)));
                }
#pragma unroll
                for (int mi = 0; mi < 2; mi++)
#pragma unroll
                    for (int ni = 0; ni < 8; ni++) mma_f16(acc[mi][ni], a[mi], bfr[ni]);
            }
            s = (s + 1) % STAGES;
        }

        // ---- epilogue for tile `cur` (overlaps next tile's in-flight loads) ----
        {
            int m_base = (cur & 31) * BM;
            int n_base = (cur >> 5) * BN;
            int qrow = lane >> 2;
            int qcol = (lane & 3) * 2;
#pragma unroll
            for (int mi = 0; mi < 2; mi++) {
                int r0 = m_base + wm * 32 + mi * 16 + qrow;
#pragma unroll
                for (int ni = 0; ni < 8; ni++) {
                    int c = n_base + wn * 64 + ni * 8 + qcol;
                    float2 bb = *reinterpret_cast<const float2*>(bias + c);
                    float2 v0, v1;
                    v0.x = acc[mi][ni][0] + bb.x;
                    v0.y = acc[mi][ni][1] + bb.y;
                    v1.x = acc[mi][ni][2] + bb.x;
                    v1.y = acc[mi][ni][3] + bb.y;
                    *reinterpret_cast<float2*>(out + (size_t)r0 * DIMM + c) = v0;
                    *reinterpret_cast<float2*>(out + (size_t)(r0 + 8) * DIMM + c) = v1;
                    acc[mi][ni][0] = 0.f; acc[mi][ni][1] = 0.f;
                    acc[mi][ni][2] = 0.f; acc[mi][ni][3] = 0.f;
                }
            }
        }

        int nt = s_next;
        if (nt >= NTILES) break;
        cur = nt;
        gA = baseA + (size_t)(cur & 31) * (BM * DIMM * 2);
        gB = baseB + (size_t)(cur >> 5) * (BN * DIMM * 2);
        __syncthreads();  // all threads read s_next before overwrite
        if (tid == 0) s_next = atomicAdd(&g_ctr, 1);
        // (next read of s_next happens after this tile's kit-0 barrier)
    }
}

// ------------------------- launch ------------------------------------------

extern "C" void kernel_launch(void* const* d_in, const int* in_sizes, int n_in,
                              void* d_out, int out_size) {
    const float* x = (const float*)d_in[0];
    const float* W = (const float*)d_in[1];
    const float* b = (const float*)d_in[2];
    float* out = (float*)d_out;

    cudaFuncSetAttribute(bgemm_kernel, cudaFuncAttributeMaxDynamicSharedMemorySize, SMEM_TOTAL);

    prep_kernel<<<12288, 256>>>(x, W);
    bgemm_kernel<<<GRID, 256, SMEM_TOTAL>>>(b, out);
}